// round 12
// baseline (speedup 1.0000x reference)
#include <cuda_runtime.h>
#include <cuda_bf16.h>

// Problem constants (fixed by the reference).
#define BB   2
#define DD   96
#define HH   96
#define WW   96
#define CIN  16
#define COUT 32
#define NK   27
#define GRIDVOL (BB*DD*HH*WW)      // 1,769,472

#define NBIN  26                   // 27 offsets minus the center (k=13)
#define NCAP  32768
#define CHUNK 64

#define CONV_BLOCKS  740           // 148 SMs * 5 blocks (forced <=51 regs)
#define CONV_THREADS 256
#define NWARP (CONV_THREADS/32)
#define TOTW (CONV_BLOCKS*NWARP)   // 5920 warps

typedef unsigned long long u64;

// Scratch (static __device__ arrays: allocation-free).
__device__ int   g_grid[GRIDVOL];              // voxel -> point id, -1 empty
__device__ u64   g_wk2[NK * (CIN/2) * COUT];   // [k][ci2][co] packed f32x2
__device__ int   g_cnt[NBIN];
__device__ int2  g_pairs[(long)NBIN * NCAP];   // (in_idx, out_idx)

// ---------------------------------------------------------------------------
// Packed f32x2 helpers (sm_103a FFMA2 path).
__device__ __forceinline__ u64 fma2(u64 a, u64 b, u64 c) {
    u64 d; asm("fma.rn.f32x2 %0, %1, %2, %3;" : "=l"(d) : "l"(a), "l"(b), "l"(c));
    return d;
}
__device__ __forceinline__ u64 mul2(u64 a, u64 b) {
    u64 d; asm("mul.rn.f32x2 %0, %1, %2;" : "=l"(d) : "l"(a), "l"(b));
    return d;
}
__device__ __forceinline__ u64 add2(u64 a, u64 b) {
    u64 d; asm("add.rn.f32x2 %0, %1, %2;" : "=l"(d) : "l"(a), "l"(b));
    return d;
}
__device__ __forceinline__ float hsum2(u64 a) {
    unsigned lo, hi;
    asm("mov.b64 {%0, %1}, %2;" : "=r"(lo), "=r"(hi) : "l"(a));
    return __uint_as_float(lo) + __uint_as_float(hi);
}

// 16-channel dot product from a 64B smem row (broadcast LDS.128 x4).
__device__ __forceinline__ float dot16s(const ulonglong2* sp, const u64* w) {
    ulonglong2 f0 = sp[0], f1 = sp[1], f2 = sp[2], f3 = sp[3];
    u64 s0 = mul2(f0.x, w[0]);
    u64 s1 = mul2(f0.y, w[1]);
    s0 = fma2(f1.x, w[2], s0);
    s1 = fma2(f1.y, w[3], s1);
    s0 = fma2(f2.x, w[4], s0);
    s1 = fma2(f2.y, w[5], s1);
    s0 = fma2(f3.x, w[6], s0);
    s1 = fma2(f3.y, w[7], s1);
    return hsum2(add2(s0, s1));
}

// ---------------------------------------------------------------------------
// Scatter point ids + repack weights + zero counters, one launch.
__global__ void setup_kernel(const int4* __restrict__ idx, int n, int nsb,
                             const float* __restrict__ w) {
    if ((int)blockIdx.x < nsb) {
        int p = blockIdx.x * blockDim.x + threadIdx.x;
        if (p < n) {
            int4 q = idx[p];  // b, z, y, x
            g_grid[((q.x * DD + q.y) * HH + q.z) * WW + q.w] = p;
        }
    } else {
        int t = (blockIdx.x - nsb) * blockDim.x + threadIdx.x;
        if (blockIdx.x == (unsigned)nsb && threadIdx.x < NBIN)
            g_cnt[threadIdx.x] = 0;
        if (t < NK * (CIN/2) * COUT) {
            int k   = t / ((CIN/2) * COUT);
            int r   = t % ((CIN/2) * COUT);
            int ci2 = r / COUT;
            int co  = r % COUT;
            float w0 = w[(co * CIN + 2*ci2    ) * NK + k];
            float w1 = w[(co * CIN + 2*ci2 + 1) * NK + k];
            g_wk2[t] = ((u64)__float_as_uint(w1) << 32) | __float_as_uint(w0);
        }
    }
}

// ---------------------------------------------------------------------------
// Build 26 off-center pair lists (smem staging, one aggregated global
// atomic per bin per block).
__global__ __launch_bounds__(256)
void probe_kernel(const int4* __restrict__ idx, int n) {
    __shared__ int  scnt[NBIN];
    __shared__ int  sbase[NBIN];
    __shared__ int2 srec[NBIN * CHUNK];

    int tid = threadIdx.x, lane = tid & 31, warp = tid >> 5;
    if (tid < NBIN) scnt[tid] = 0;
    __syncthreads();

    int kk = lane < 13 ? lane : lane + 1;
    int dz = kk / 9 - 1, dy = (kk / 3) % 3 - 1, dx = kk % 3 - 1;
    int p0 = blockIdx.x * CHUNK + warp * (CHUNK / 8);

#pragma unroll
    for (int r = 0; r < CHUNK / 8; r++) {
        int p = p0 + r;
        if (p < n && lane < NBIN) {
            int4 q = __ldg(&idx[p]);
            int zz = q.y + dz, yy = q.z + dy, xx = q.w + dx;
            if ((unsigned)zz < (unsigned)DD &&
                (unsigned)yy < (unsigned)HH &&
                (unsigned)xx < (unsigned)WW) {
                int j = __ldg(&g_grid[((q.x * DD + zz) * HH + yy) * WW + xx]);
                if (j >= 0) {
                    int pos = atomicAdd(&scnt[lane], 1);
                    srec[lane * CHUNK + pos] = make_int2(j, p);
                }
            }
        }
    }
    __syncthreads();
    if (tid < NBIN) sbase[tid] = atomicAdd(&g_cnt[tid], scnt[tid]);
    __syncthreads();
    for (int t = tid; t < NBIN * CHUNK; t += 256) {
        int b = t / CHUNK, i = t % CHUNK;
        if (i < scnt[b]) {
            int s = sbase[b] + i;
            if (s < NCAP) g_pairs[(long)b * NCAP + s] = srec[t];
        }
    }
}

// ---------------------------------------------------------------------------
// Center + bias. Warp handles 8 consecutive points per batch:
// stage (coalesced LDG.128) -> broadcast LDS compute. Double-buffered.
__global__ __launch_bounds__(CONV_THREADS, 5)
void center_kernel(const uint4* __restrict__ feat4,
                   const float* __restrict__ bias,
                   float* __restrict__ out, int n) {
    __shared__ uint4 sbuf[NWARP][2][32];
    int lane = threadIdx.x & 31;
    int warp = threadIdx.x >> 5;
    int w = blockIdx.x * NWARP + warp;

    u64 wk[8];
#pragma unroll
    for (int i = 0; i < 8; i++) wk[i] = g_wk2[(13 * 8 + i) * COUT + lane];
    float b0 = __ldg(&bias[lane]);

    const int stride = TOTW * 8;
    int p0 = w * 8;
    if (p0 >= n) return;

    int pidx = min(p0 + (lane >> 2), n - 1);
    uint4 q = __ldg(&feat4[pidx * 4 + (lane & 3)]);

    int pb = 0;
    for (; p0 < n; p0 += stride, pb ^= 1) {
        sbuf[warp][pb][lane] = q;
        int p1 = p0 + stride;
        if (p1 < n) {
            int pn = min(p1 + (lane >> 2), n - 1);
            q = __ldg(&feat4[pn * 4 + (lane & 3)]);
        }
        __syncwarp();
        const ulonglong2* sp = (const ulonglong2*)sbuf[warp][pb];
        int jmax = min(8, n - p0);
#pragma unroll
        for (int j = 0; j < 8; j++) {
            if (j < jmax) {
                float s = dot16s(sp + j * 4, wk);
                out[(long)(p0 + j) * COUT + lane] = b0 + s;
            }
        }
        __syncwarp();
    }
}

// ---------------------------------------------------------------------------
// Pair conv: warp pinned to one bin; 8 pairs per batch; staged loads +
// broadcast LDS compute; one contiguous atomicAdd per pair.
__global__ __launch_bounds__(CONV_THREADS, 5)
void pair_conv_kernel(const uint4* __restrict__ feat4,
                      float* __restrict__ out) {
    __shared__ uint4 sbuf[NWARP][2][32];
    int lane = threadIdx.x & 31;
    int warp = threadIdx.x >> 5;
    int w = blockIdx.x * NWARP + warp;
    int b = w % NBIN, slice = w / NBIN;
    int nwk = (TOTW - b + NBIN - 1) / NBIN;
    int kk = b < 13 ? b : b + 1;

    u64 wk[8];
#pragma unroll
    for (int i = 0; i < 8; i++) wk[i] = g_wk2[(kk * 8 + i) * COUT + lane];

    int cnt = min(g_cnt[b], NCAP);
    const int2* pr = g_pairs + (long)b * NCAP;
    int chunk = (((cnt + nwk - 1) / nwk) + 7) & ~7;   // multiple of 8
    int i0 = slice * chunk;
    int i1 = min(cnt, i0 + chunk);
    if (i0 >= i1) return;

    int ridx = min(i0 + (lane >> 2), i1 - 1);
    int2 rcur = __ldg(&pr[ridx]);
    uint4 q = __ldg(&feat4[rcur.x * 4 + (lane & 3)]);

    int pb = 0;
    for (int i = i0; i < i1; i += 8, pb ^= 1) {
        sbuf[warp][pb][lane] = q;
        int2 rnext;
        int inext = i + 8;
        if (inext < i1) {
            int rn = min(inext + (lane >> 2), i1 - 1);
            rnext = __ldg(&pr[rn]);
            q = __ldg(&feat4[rnext.x * 4 + (lane & 3)]);
        }
        __syncwarp();
        const ulonglong2* sp = (const ulonglong2*)sbuf[warp][pb];
        int jmax = min(8, i1 - i);
#pragma unroll
        for (int j = 0; j < 8; j++) {
            if (j < jmax) {
                int oy = __shfl_sync(0xffffffffu, rcur.y, j * 4);
                float s = dot16s(sp + j * 4, wk);
                atomicAdd(&out[(long)oy * COUT + lane], s);
            }
        }
        __syncwarp();
        rcur = rnext;
    }
}

// ---------------------------------------------------------------------------
extern "C" void kernel_launch(void* const* d_in, const int* in_sizes, int n_in,
                              void* d_out, int out_size) {
    const float* feat = (const float*)d_in[0];   // [n,16] f32
    const int*   idx  = (const int*)d_in[1];     // [n,4]  i32
    const float* w    = (const float*)d_in[2];   // [32,16,3,3,3] f32
    const float* bias = (const float*)d_in[3];   // [32] f32
    int n = in_sizes[1] / 4;

    void* gptr = nullptr; cudaGetSymbolAddress(&gptr, g_grid);
    cudaMemsetAsync(gptr, 0xFF, sizeof(int) * (size_t)GRIDVOL);          // act 1

    int nsb = (n + 255) / 256;
    int nwb = (NK * (CIN/2) * COUT + 255) / 256;
    setup_kernel<<<nsb + nwb, 256>>>((const int4*)idx, n, nsb, w);       // act 2
    probe_kernel<<<(n + CHUNK - 1) / CHUNK, 256>>>((const int4*)idx, n); // act 3
    center_kernel<<<CONV_BLOCKS, CONV_THREADS>>>(
        (const uint4*)feat, bias, (float*)d_out, n);                     // act 4
    pair_conv_kernel<<<CONV_BLOCKS, CONV_THREADS>>>(
        (const uint4*)feat, (float*)d_out);                              // act 5 (profiled)
}

// round 13
// speedup vs baseline: 1.1674x; 1.1674x over previous
#include <cuda_runtime.h>
#include <cuda_bf16.h>

// Problem constants (fixed by the reference).
#define BB   2
#define DD   96
#define HH   96
#define WW   96
#define CIN  16
#define COUT 32
#define NK   27
#define GRIDVOL (BB*DD*HH*WW)      // 1,769,472

#define NBIN  26                   // 27 offsets minus the center (k=13)
#define NCAP  32768
#define CHUNK 64                   // points per probe block (8 warps x 8 pts)

#define PAIR_BLOCKS  740           // 148 SMs * 5 blocks (48 regs via lb)
#define PAIR_THREADS 256
#define PNWARP (PAIR_THREADS/32)
#define PTOTW (PAIR_BLOCKS*PNWARP) // 5920 warps

typedef unsigned long long u64;

// Scratch (static __device__ arrays: allocation-free).
__device__ int   g_grid[GRIDVOL];              // voxel -> point id, -1 empty
__device__ u64   g_wk2[NK * (CIN/2) * COUT];   // [k][ci2][co] packed f32x2
__device__ int   g_cnt[NBIN];
__device__ int2  g_pairs[(long)NBIN * NCAP];   // (in_idx, out_idx)

// ---------------------------------------------------------------------------
// Packed f32x2 helpers (sm_103a FFMA2 path).
__device__ __forceinline__ u64 fma2(u64 a, u64 b, u64 c) {
    u64 d; asm("fma.rn.f32x2 %0, %1, %2, %3;" : "=l"(d) : "l"(a), "l"(b), "l"(c));
    return d;
}
__device__ __forceinline__ u64 mul2(u64 a, u64 b) {
    u64 d; asm("mul.rn.f32x2 %0, %1, %2;" : "=l"(d) : "l"(a), "l"(b));
    return d;
}
__device__ __forceinline__ u64 add2(u64 a, u64 b) {
    u64 d; asm("add.rn.f32x2 %0, %1, %2;" : "=l"(d) : "l"(a), "l"(b));
    return d;
}
__device__ __forceinline__ float hsum2(u64 a) {
    unsigned lo, hi;
    asm("mov.b64 {%0, %1}, %2;" : "=r"(lo), "=r"(hi) : "l"(a));
    return __uint_as_float(lo) + __uint_as_float(hi);
}

// 16-channel dot product from a 64B smem row (broadcast LDS.128 x4).
__device__ __forceinline__ float dot16s(const ulonglong2* sp, const u64* w) {
    ulonglong2 f0 = sp[0], f1 = sp[1], f2 = sp[2], f3 = sp[3];
    u64 s0 = mul2(f0.x, w[0]);
    u64 s1 = mul2(f0.y, w[1]);
    s0 = fma2(f1.x, w[2], s0);
    s1 = fma2(f1.y, w[3], s1);
    s0 = fma2(f2.x, w[4], s0);
    s1 = fma2(f2.y, w[5], s1);
    s0 = fma2(f3.x, w[6], s0);
    s1 = fma2(f3.y, w[7], s1);
    return hsum2(add2(s0, s1));
}

// ---------------------------------------------------------------------------
// Scatter point ids + repack weights + zero counters, one launch.
__global__ void setup_kernel(const int4* __restrict__ idx, int n, int nsb,
                             const float* __restrict__ w) {
    if ((int)blockIdx.x < nsb) {
        int p = blockIdx.x * blockDim.x + threadIdx.x;
        if (p < n) {
            int4 q = idx[p];  // b, z, y, x
            g_grid[((q.x * DD + q.y) * HH + q.z) * WW + q.w] = p;
        }
    } else {
        int t = (blockIdx.x - nsb) * blockDim.x + threadIdx.x;
        if (blockIdx.x == (unsigned)nsb && threadIdx.x < NBIN)
            g_cnt[threadIdx.x] = 0;
        if (t < NK * (CIN/2) * COUT) {
            int k   = t / ((CIN/2) * COUT);
            int r   = t % ((CIN/2) * COUT);
            int ci2 = r / COUT;
            int co  = r % COUT;
            float w0 = w[(co * CIN + 2*ci2    ) * NK + k];
            float w1 = w[(co * CIN + 2*ci2 + 1) * NK + k];
            g_wk2[t] = ((u64)__float_as_uint(w1) << 32) | __float_as_uint(w0);
        }
    }
}

// ---------------------------------------------------------------------------
// FUSED probe + center. Each warp owns 8 points:
//  - issues the feature-row LDG up front (in flight during the probes)
//  - probes the 26 off-center offsets, staging hits in smem
//  - computes out[p] = bias + W13*feat[p] while probe flush waits
// Center's fma/L1 work fills the probe's memory-stall slots.
__global__ __launch_bounds__(256)
void probe_center_kernel(const int4* __restrict__ idx,
                         const uint4* __restrict__ feat4,
                         const float* __restrict__ bias,
                         float* __restrict__ out, int n) {
    __shared__ int  scnt[NBIN];
    __shared__ int  sbase[NBIN];
    __shared__ int2 srec[NBIN * CHUNK];
    __shared__ uint4 csbuf[8][32];              // per-warp 8-row feature stage

    int tid = threadIdx.x, lane = tid & 31, warp = tid >> 5;
    if (tid < NBIN) scnt[tid] = 0;

    // Center weights + bias (L2-hot; overlaps everything below).
    u64 wk[8];
#pragma unroll
    for (int i = 0; i < 8; i++) wk[i] = g_wk2[(13 * 8 + i) * COUT + lane];
    float b0 = __ldg(&bias[lane]);

    int p0 = blockIdx.x * CHUNK + warp * 8;     // this warp's 8 points
    // Feature stage LDG issued first -> in flight during the probes.
    uint4 q = make_uint4(0, 0, 0, 0);
    if (p0 < n) {
        int pidx = min(p0 + (lane >> 2), n - 1);
        q = __ldg(&feat4[pidx * 4 + (lane & 3)]);
    }
    __syncthreads();                             // scnt ready

    int kk = lane < 13 ? lane : lane + 1;
    int dz = kk / 9 - 1, dy = (kk / 3) % 3 - 1, dx = kk % 3 - 1;

#pragma unroll
    for (int r = 0; r < 8; r++) {
        int p = p0 + r;
        if (p < n && lane < NBIN) {
            int4 qi = __ldg(&idx[p]);
            int zz = qi.y + dz, yy = qi.z + dy, xx = qi.w + dx;
            if ((unsigned)zz < (unsigned)DD &&
                (unsigned)yy < (unsigned)HH &&
                (unsigned)xx < (unsigned)WW) {
                int j = __ldg(&g_grid[((qi.x * DD + zz) * HH + yy) * WW + xx]);
                if (j >= 0) {
                    int pos = atomicAdd(&scnt[lane], 1);
                    srec[lane * CHUNK + pos] = make_int2(j, p);
                }
            }
        }
    }

    // Center compute for this warp's 8 points (no cross-warp deps).
    if (p0 < n) {
        csbuf[warp][lane] = q;
        __syncwarp();
        const ulonglong2* sp = (const ulonglong2*)csbuf[warp];
        int jmax = min(8, n - p0);
#pragma unroll
        for (int j = 0; j < 8; j++) {
            if (j < jmax) {
                float s = dot16s(sp + j * 4, wk);
                out[(long)(p0 + j) * COUT + lane] = b0 + s;
            }
        }
    }

    __syncthreads();
    if (tid < NBIN) sbase[tid] = atomicAdd(&g_cnt[tid], scnt[tid]);
    __syncthreads();
    for (int t = tid; t < NBIN * CHUNK; t += 256) {
        int b = t / CHUNK, i = t % CHUNK;
        if (i < scnt[b]) {
            int s = sbase[b] + i;
            if (s < NCAP) g_pairs[(long)b * NCAP + s] = srec[t];
        }
    }
}

// ---------------------------------------------------------------------------
// Pair conv: warp pinned to one bin; 8 pairs per batch; staged loads +
// broadcast LDS compute; one contiguous atomicAdd per pair.
// Validated config: grid 740, forced 5 blocks/SM (48 regs).
__global__ __launch_bounds__(PAIR_THREADS, 5)
void pair_conv_kernel(const uint4* __restrict__ feat4,
                      float* __restrict__ out) {
    __shared__ uint4 sbuf[PNWARP][2][32];
    int lane = threadIdx.x & 31;
    int warp = threadIdx.x >> 5;
    int w = blockIdx.x * PNWARP + warp;
    int b = w % NBIN, slice = w / NBIN;
    int nwk = (PTOTW - b + NBIN - 1) / NBIN;
    int kk = b < 13 ? b : b + 1;

    u64 wk[8];
#pragma unroll
    for (int i = 0; i < 8; i++) wk[i] = g_wk2[(kk * 8 + i) * COUT + lane];

    int cnt = min(g_cnt[b], NCAP);
    const int2* pr = g_pairs + (long)b * NCAP;
    int chunk = (((cnt + nwk - 1) / nwk) + 7) & ~7;   // multiple of 8
    int i0 = slice * chunk;
    int i1 = min(cnt, i0 + chunk);
    if (i0 >= i1) return;

    int ridx = min(i0 + (lane >> 2), i1 - 1);
    int2 rcur = __ldg(&pr[ridx]);
    uint4 q = __ldg(&feat4[rcur.x * 4 + (lane & 3)]);

    int pb = 0;
    for (int i = i0; i < i1; i += 8, pb ^= 1) {
        sbuf[warp][pb][lane] = q;
        int2 rnext;
        int inext = i + 8;
        if (inext < i1) {
            int rn = min(inext + (lane >> 2), i1 - 1);
            rnext = __ldg(&pr[rn]);
            q = __ldg(&feat4[rnext.x * 4 + (lane & 3)]);
        }
        __syncwarp();
        const ulonglong2* sp = (const ulonglong2*)sbuf[warp][pb];
        int jmax = min(8, i1 - i);
#pragma unroll
        for (int j = 0; j < 8; j++) {
            if (j < jmax) {
                int oy = __shfl_sync(0xffffffffu, rcur.y, j * 4);
                float s = dot16s(sp + j * 4, wk);
                atomicAdd(&out[(long)oy * COUT + lane], s);
            }
        }
        __syncwarp();
        rcur = rnext;
    }
}

// ---------------------------------------------------------------------------
extern "C" void kernel_launch(void* const* d_in, const int* in_sizes, int n_in,
                              void* d_out, int out_size) {
    const float* feat = (const float*)d_in[0];   // [n,16] f32
    const int*   idx  = (const int*)d_in[1];     // [n,4]  i32
    const float* w    = (const float*)d_in[2];   // [32,16,3,3,3] f32
    const float* bias = (const float*)d_in[3];   // [32] f32
    int n = in_sizes[1] / 4;

    void* gptr = nullptr; cudaGetSymbolAddress(&gptr, g_grid);
    cudaMemsetAsync(gptr, 0xFF, sizeof(int) * (size_t)GRIDVOL);            // act 1

    int nsb = (n + 255) / 256;
    int nwb = (NK * (CIN/2) * COUT + 255) / 256;
    setup_kernel<<<nsb + nwb, 256>>>((const int4*)idx, n, nsb, w);         // act 2
    probe_center_kernel<<<(n + CHUNK - 1) / CHUNK, 256>>>(
        (const int4*)idx, (const uint4*)feat, bias, (float*)d_out, n);     // act 3
    pair_conv_kernel<<<PAIR_BLOCKS, PAIR_THREADS>>>(
        (const uint4*)feat, (float*)d_out);                                // act 4
}